// round 12
// baseline (speedup 1.0000x reference)
#include <cuda_runtime.h>

// out4[((b*H+y)*W+x)*768 + ch*4 + i] = float4{ in[b,ch,y+i-3, x-2..x+1] },
// zero-padded; lanes z,w zeroed when i==3. B=8, C=192, H=W=48.
// Block = (b, y, 12-wide x-tile, 48-channel quarter). Smem: [192 chi][15] = 11520 B.
// Store phase: exactly ONE chi per thread (short register lifetimes).

#define B_     8
#define C_     192
#define H_     48
#define W_     48
#define TX     12
#define XT     (W_ / TX)            // 4 x-tiles
#define CSPL   4                    // channel splits per position
#define CH     (C_ / CSPL)          // 48 channels per block
#define ROWS   (CH * 4)             // 192 chi rows per block
#define PITCH  15                   // cols x0-2 .. x0+12 ; gcd(15,32)=1
#define SELEMS (ROWS * PITCH)       // 2880 floats = 11520 B
#define NTHR   192
#define LOAD_ITERS (SELEMS / NTHR)  // 15

__global__ void __launch_bounds__(NTHR)
block_sample_smem(const float* __restrict__ in, float4* __restrict__ out)
{
    __shared__ float s[SELEMS];

    const int tid = threadIdx.x;
    int bid = blockIdx.x;
    const int cs = bid & 3;   bid >>= 2;        // channel quarter
    const int xt = bid % XT;  bid /= XT;
    const int y  = bid % H_;
    const int b  = bid / H_;
    const int x0 = xt * TX;
    const int ch0 = cs * CH;

    // ---- load: rows y-3..y, cols x0-2..x0+12, channels ch0..ch0+47 ----
    #pragma unroll
    for (int k = 0; k < LOAD_ITERS; k++) {
        const int idx = k * NTHR + tid;
        const int sc  = idx % PITCH;       // 0..14
        const int rf  = idx / PITCH;       // ch_local*4 + r
        const int gy  = y + (rf & 3) - 3;  // <= 47 always
        const int gx  = x0 - 2 + sc;       // -2 .. 48
        float v = 0.f;
        if (gy >= 0 && gx >= 0 && gx < W_)
            v = __ldg(in + ((b * C_ + ch0 + (rf >> 2)) * H_ + gy) * W_ + gx);
        s[idx] = v;
    }
    __syncthreads();

    // ---- store: one chi per thread; read 15-word window (conflict-free LDS),
    //      emit 12 independent, coalesced streaming STG.128 ----
    const int chi = tid;                               // ch_local*4 + i
    const bool msk = (chi & 3) == 3;                   // i == 3 -> mask z,w
    const float* row = &s[chi * PITCH];

    float w[PITCH], wm[PITCH];
    #pragma unroll
    for (int c = 0; c < PITCH; c++) w[c] = row[c];
    #pragma unroll
    for (int c = 0; c < PITCH; c++) wm[c] = msk ? 0.f : w[c];

    float4* o = out + (long)((b * H_ + y) * W_ + x0) * (C_ * 4) + ch0 * 4 + chi;
    #pragma unroll
    for (int xl = 0; xl < TX; xl++) {
        __stcs(o + xl * (C_ * 4),
               make_float4(w[xl], w[xl + 1], wm[xl + 2], wm[xl + 3]));
    }
}

extern "C" void kernel_launch(void* const* d_in, const int* in_sizes, int n_in,
                              void* d_out, int out_size)
{
    const float* in  = (const float*)d_in[0];
    float4*      out = (float4*)d_out;

    const int blocks = B_ * H_ * XT * CSPL;   // 6144
    block_sample_smem<<<blocks, NTHR>>>(in, out);
}

// round 13
// speedup vs baseline: 1.0156x; 1.0156x over previous
#include <cuda_runtime.h>

// out4[((b*H+y)*W+x)*768 + ch*4 + i] = float4{ in[b,ch,y+i-3, x-2..x+1] },
// zero-padded; lanes z,w zeroed when i==3. B=8, C=192, H=W=48.
// Block = (b, y, 12-wide x-tile, 48-channel quarter). Smem: [192 chi][15] = 11520 B.
// One chi per thread; mask applied inline (no second window copy -> fewer regs).

#define B_     8
#define C_     192
#define H_     48
#define W_     48
#define TX     12
#define XT     (W_ / TX)            // 4 x-tiles
#define CSPL   4                    // channel splits per position
#define CH     (C_ / CSPL)          // 48 channels per block
#define ROWS   (CH * 4)             // 192 chi rows per block
#define PITCH  15                   // cols x0-2 .. x0+12 ; gcd(15,32)=1
#define SELEMS (ROWS * PITCH)       // 2880 floats = 11520 B
#define NTHR   192
#define LOAD_ITERS (SELEMS / NTHR)  // 15

__global__ void __launch_bounds__(NTHR)
block_sample_smem(const float* __restrict__ in, float4* __restrict__ out)
{
    __shared__ float s[SELEMS];

    const int tid = threadIdx.x;
    int bid = blockIdx.x;
    const int cs = bid & 3;   bid >>= 2;        // channel quarter
    const int xt = bid % XT;  bid /= XT;
    const int y  = bid % H_;
    const int b  = bid / H_;
    const int x0 = xt * TX;
    const int ch0 = cs * CH;

    // ---- load: rows y-3..y, cols x0-2..x0+12, channels ch0..ch0+47 ----
    #pragma unroll
    for (int k = 0; k < LOAD_ITERS; k++) {
        const int idx = k * NTHR + tid;
        const int sc  = idx % PITCH;       // 0..14
        const int rf  = idx / PITCH;       // ch_local*4 + r
        const int gy  = y + (rf & 3) - 3;  // <= 47 always
        const int gx  = x0 - 2 + sc;       // -2 .. 48
        float v = 0.f;
        if (gy >= 0 && gx >= 0 && gx < W_)
            v = __ldg(in + ((b * C_ + ch0 + (rf >> 2)) * H_ + gy) * W_ + gx);
        s[idx] = v;
    }
    __syncthreads();

    // ---- store: one chi per thread; 15-word window (conflict-free LDS),
    //      12 coalesced streaming STG.128 with inline i==3 masking ----
    const int chi = tid;                               // ch_local*4 + i
    const bool msk = (chi & 3) == 3;                   // i == 3 -> mask z,w
    const float* row = &s[chi * PITCH];

    float w[PITCH];
    #pragma unroll
    for (int c = 0; c < PITCH; c++) w[c] = row[c];

    float4* o = out + (long)((b * H_ + y) * W_ + x0) * (C_ * 4) + ch0 * 4 + chi;
    #pragma unroll
    for (int xl = 0; xl < TX; xl++) {
        __stcs(o + xl * (C_ * 4),
               make_float4(w[xl],
                           w[xl + 1],
                           msk ? 0.f : w[xl + 2],
                           msk ? 0.f : w[xl + 3]));
    }
}

extern "C" void kernel_launch(void* const* d_in, const int* in_sizes, int n_in,
                              void* d_out, int out_size)
{
    const float* in  = (const float*)d_in[0];
    float4*      out = (float4*)d_out;

    const int blocks = B_ * H_ * XT * CSPL;   // 6144
    block_sample_smem<<<blocks, NTHR>>>(in, out);
}